// round 10
// baseline (speedup 1.0000x reference)
#include <cuda_runtime.h>
#include <cstdint>

// FixedGaussianBlur: depthwise 21x21 Gaussian (sigma=3), reflect padding,
// x[32,3,512,512] f32 -> y[32,3,512,512] f32.
// R8 structure (best: 64.2us) + occupancy push to 4 blocks/SM:
//  - 148x84 in-place smem tile, stride 84 (perfect LDS.128 bank-quad tiling
//    for 8-consecutive-row octets).
//  - Horizontal: scalar FFMA-imm (rt=1, per-FMA optimal), two 8-output chunks
//    per unit to keep live regs ~30 (fits the 32-reg/4-block budget).
//  - Vertical: packed fma.rn.f32x2 over col pairs (fewer issue slots + LDS).

#define IMG_W 512
#define IMG_H 512
#define PAD 10
#define KS 21
#define TW 64
#define TH 128
#define SROWS 148
#define SCOLS 84
#define NTHREADS 512
#define NIMG 96
#define NU64 (SROWS * SCOLS / 2)        // 6216
#define SMEM_BYTES (SROWS * SCOLS * 4)  // 49728

#define W0  0.13303900f
#define W1  0.12584950f
#define W2  0.10652928f
#define W3  0.08069223f
#define W4  0.05469397f
#define W5  0.03317359f
#define W6  0.01800488f
#define W7  0.00874446f
#define W8  0.00380033f
#define W9  0.00147793f
#define W10 0.00051432f

__device__ __forceinline__ float tap(int j) {
    constexpr float w[KS] = {W10, W9, W8, W7, W6, W5, W4, W3, W2, W1, W0,
                             W1, W2, W3, W4, W5, W6, W7, W8, W9, W10};
    return w[j];
}

__device__ __forceinline__ int reflect_idx(int i, int n) {
    i = (i < 0) ? -i : i;
    i = (i >= n) ? (2 * n - 2 - i) : i;
    return i;
}

__device__ __forceinline__ uint64_t bcast2(float f) {
    uint32_t b = __float_as_uint(f);
    return ((uint64_t)b << 32) | (uint64_t)b;
}

__device__ __forceinline__ void ffma2(uint64_t& d, uint64_t a, uint64_t b, uint64_t c) {
    asm("fma.rn.f32x2 %0, %1, %2, %3;" : "=l"(d) : "l"(a), "l"(b), "l"(c));
}

// 8-output horizontal filter: reads srow[0..27] (7 LDS.128), scalar FFMA-imm.
// Live regs ~29 -> two sequential calls fit a 32-reg budget with minimal spill.
__device__ __forceinline__ void hfilter8(const float* srow, float o[8]) {
    float v[28];
    const float4* p = reinterpret_cast<const float4*>(srow);
    #pragma unroll
    for (int q = 0; q < 7; ++q) {
        float4 t = p[q];
        v[4 * q + 0] = t.x; v[4 * q + 1] = t.y;
        v[4 * q + 2] = t.z; v[4 * q + 3] = t.w;
    }
    #pragma unroll
    for (int c = 0; c < 8; ++c) {
        float acc = v[c] * tap(0);
        #pragma unroll
        for (int j = 1; j < KS; ++j) acc = fmaf(v[c + j], tap(j), acc);
        o[c] = acc;
    }
}

__global__ __launch_bounds__(NTHREADS, 4)
void gauss_blur_fused(const float* __restrict__ in, float* __restrict__ out) {
    extern __shared__ __align__(16) float s[];   // [SROWS][SCOLS]

    const int tid = threadIdx.x;
    const int x0 = blockIdx.x * TW;
    const int y0 = blockIdx.y * TH;
    const float* __restrict__ base = in + (size_t)blockIdx.z * (IMG_W * IMG_H);

    // ---- Load 148x84 tile ----
    const bool x_int = (x0 >= PAD) && (x0 + TW + PAD <= IMG_W);
    if (x_int) {
        int idx = tid;
        #pragma unroll
        for (int it = 0; it < (NU64 + NTHREADS - 1) / NTHREADS; ++it) {
            if (idx < NU64) {
                int r = idx / (SCOLS / 2);
                int c2 = idx - r * (SCOLS / 2);
                int gy = reflect_idx(y0 - PAD + r, IMG_H);
                uint64_t v = __ldg((const uint64_t*)(base + (size_t)gy * IMG_W
                                                     + (x0 - PAD) + 2 * c2));
                *reinterpret_cast<uint64_t*>(&s[r * SCOLS + 2 * c2]) = v;
            }
            idx += NTHREADS;
        }
    } else {
        int idx = tid;
        #pragma unroll
        for (int it = 0; it < (SROWS * SCOLS + NTHREADS - 1) / NTHREADS; ++it) {
            if (idx < SROWS * SCOLS) {
                int r = idx / SCOLS;
                int c = idx - r * SCOLS;
                int gy = reflect_idx(y0 - PAD + r, IMG_H);
                int gx = reflect_idx(x0 - PAD + c, IMG_W);
                s[r * SCOLS + c] = __ldg(base + (size_t)gy * IMG_W + gx);
            }
            idx += NTHREADS;
        }
    }
    __syncthreads();

    // ---- Horizontal pass, in place, conflict-free octet mapping ----
    // P1: rows 0..127 (row=tid&127, seg=(tid>>7)*16), two 8-out chunks.
    // P2: rows 128..147, 80 units (row=128+tid%20, seg=(tid/20)*16).
    {
        const int row1 = tid & 127;
        const int seg1 = (tid >> 7) << 4;
        float oA[8], oB[8];
        hfilter8(&s[row1 * SCOLS + seg1], oA);
        hfilter8(&s[row1 * SCOLS + seg1 + 8], oB);
        __syncthreads();   // all P1 reads of raw tile complete
        {
            float4* q = reinterpret_cast<float4*>(&s[row1 * SCOLS + seg1]);
            q[0] = make_float4(oA[0], oA[1], oA[2], oA[3]);
            q[1] = make_float4(oA[4], oA[5], oA[6], oA[7]);
            q[2] = make_float4(oB[0], oB[1], oB[2], oB[3]);
            q[3] = make_float4(oB[4], oB[5], oB[6], oB[7]);
        }
        const bool p2 = (tid < 80);
        const int row2 = 128 + (tid % 20);
        const int seg2 = (tid / 20) << 4;
        float oC[8], oD[8];
        if (p2) {
            hfilter8(&s[row2 * SCOLS + seg2], oC);
            hfilter8(&s[row2 * SCOLS + seg2 + 8], oD);
        }
        __syncthreads();   // P2 reads done + P1 stores visible
        if (p2) {
            float4* q = reinterpret_cast<float4*>(&s[row2 * SCOLS + seg2]);
            q[0] = make_float4(oC[0], oC[1], oC[2], oC[3]);
            q[1] = make_float4(oC[4], oC[5], oC[6], oC[7]);
            q[2] = make_float4(oD[0], oD[1], oD[2], oD[3]);
            q[3] = make_float4(oD[4], oD[5], oD[6], oD[7]);
        }
    }
    __syncthreads();

    // ---- Vertical pass: 32 col-pairs x 16 groups of 8 rows ----
    {
        const int cp = tid & 31;
        const int g = (tid >> 5) << 3;

        uint64_t acc[8];
        #pragma unroll
        for (int o = 0; o < 8; ++o) acc[o] = 0;

        const float* col = s + 2 * cp;
        #pragma unroll
        for (int t = 0; t < 28; ++t) {
            uint64_t v2 = *reinterpret_cast<const uint64_t*>(col + (g + t) * SCOLS);
            #pragma unroll
            for (int o = 0; o < 8; ++o) {
                int j = t - o;
                if (j >= 0 && j < KS) {
                    int wi = (j <= 10) ? j : (20 - j);
                    ffma2(acc[o], v2, bcast2(tap(wi)), acc[o]);
                }
            }
        }

        char* dst = (char*)(out + (size_t)blockIdx.z * (IMG_W * IMG_H)
                                + (size_t)(y0 + g) * IMG_W + (x0 + 2 * cp));
        #pragma unroll
        for (int o = 0; o < 8; ++o)
            *reinterpret_cast<uint64_t*>(dst + (size_t)o * IMG_W * 4) = acc[o];
    }
}

extern "C" void kernel_launch(void* const* d_in, const int* in_sizes, int n_in,
                              void* d_out, int out_size) {
    (void)in_sizes; (void)n_in; (void)out_size;
    const float* x = (const float*)d_in[0];
    float* y = (float*)d_out;
    cudaFuncSetAttribute(gauss_blur_fused,
                         cudaFuncAttributeMaxDynamicSharedMemorySize, SMEM_BYTES);
    dim3 grid(IMG_W / TW, IMG_H / TH, NIMG);  // 8 x 4 x 96
    gauss_blur_fused<<<grid, NTHREADS, SMEM_BYTES>>>(x, y);
}